// round 17
// baseline (speedup 1.0000x reference)
#include <cuda_runtime.h>
#include <math.h>

#define BB 32
#define CC 64
#define LL 512
#define VV 8192
#define NTOK_MAX (BB*LL)      /* 16384 */
#define NELEM (BB*CC*LL)      /* 1048576 */
#define TR 128                /* codebook rows staged per tile */

// packed f32x2 helpers (sm_100+): lanewise IEEE fma on two packed floats
#define FMA_F32X2(d, a, b, c) \
    asm("fma.rn.f32x2 %0, %1, %2, %3;" : "=l"(d) : "l"(a), "l"(b), "l"(c))
#define UNPACK_F32X2(lo, hi, in) \
    asm("mov.b64 {%0, %1}, %2;" : "=r"(lo), "=r"(hi) : "l"(in))

// ---------------- device scratch (no malloc allowed) ----------------
__device__ float g_cbn[VV*CC];            // normalized codebook, 2MB
__device__ float g_frest[NELEM];          // residual, 4MB
__device__ float g_fhat[NELEM];           // reconstruction, 4MB
__device__ float g_rest_tok[NTOK_MAX*CC]; // downsampled+normalized tokens
__device__ unsigned long long g_key[NTOK_MAX]; // packed (ordered val, VV-idx)
__device__ float g_loss;                  // sum of squared err accum

// pack (value, idx) so u64 max == (max value, lowest idx on float-equal ties)
__device__ __forceinline__ unsigned long long pack_key(float v, int idx) {
    unsigned u = __float_as_uint(v);
    u = (u & 0x80000000u) ? ~u : (u | 0x80000000u);   // monotone order-preserving
    return ((unsigned long long)u << 32) | (unsigned)(VV - idx);
}

// ---------------- codebook row-normalize (IEEE sqrt/div, fast-math-proof) ----
__global__ void normalize_cb_kernel(const float* __restrict__ ew) {
    int row = blockIdx.x;
    int lane = threadIdx.x;                 // 32 threads, 2 floats each
    if (row == 0 && lane == 0) g_loss = 0.f;
    float2 v = reinterpret_cast<const float2*>(ew + row*CC)[lane];
    float ss = v.x*v.x + v.y*v.y;
    #pragma unroll
    for (int off = 16; off > 0; off >>= 1)
        ss += __shfl_xor_sync(0xffffffffu, ss, off);
    float den = fmaxf(__fsqrt_rn(ss), 1e-12f);
    float2 o;
    o.x = __fdiv_rn(v.x, den);
    o.y = __fdiv_rn(v.y, den);
    reinterpret_cast<float2*>(g_cbn + row*CC)[lane] = o;
}

// ---------- fused area-downsample + row-normalize + key-init ----------
// src = f (first scale) or g_frest (later scales). Accumulation order
// BIT-IDENTICAL to the validated serial loop; loads batched for MLP.
__global__ void ds_norm_kernel(const float* __restrict__ src, int s, int r, int ntok) {
    int t = blockIdx.x*8 + (threadIdx.x >> 5);
    if (t >= ntok) return;
    int lane = threadIdx.x & 31;
    int b = t / s, p = t - b*s;
    const float* s0 = src + (b*CC + 2*lane)*LL + p*r;
    const float* s1 = s0 + LL;
    float va = 0.f, vb = 0.f;
    if (r >= 16) {
        const float4* p0 = reinterpret_cast<const float4*>(s0);
        const float4* p1 = reinterpret_cast<const float4*>(s1);
        int n4 = r >> 2;
        for (int j = 0; j < n4; j += 4) {
            float4 x0 = p0[j], x1 = p0[j+1], x2 = p0[j+2], x3 = p0[j+3];
            float4 y0 = p1[j], y1 = p1[j+1], y2 = p1[j+2], y3 = p1[j+3];
            va += x0.x; vb += y0.x; va += x0.y; vb += y0.y;
            va += x0.z; vb += y0.z; va += x0.w; vb += y0.w;
            va += x1.x; vb += y1.x; va += x1.y; vb += y1.y;
            va += x1.z; vb += y1.z; va += x1.w; vb += y1.w;
            va += x2.x; vb += y2.x; va += x2.y; vb += y2.y;
            va += x2.z; vb += y2.z; va += x2.w; vb += y2.w;
            va += x3.x; vb += y3.x; va += x3.y; vb += y3.y;
            va += x3.z; vb += y3.z; va += x3.w; vb += y3.w;
        }
    } else {
        for (int j = 0; j < r; ++j) va += s0[j];
        for (int j = 0; j < r; ++j) vb += s1[j];
    }
    float inv = 1.0f / (float)r;            // r power of two -> exact
    va *= inv; vb *= inv;
    float ss = va*va + vb*vb;
    #pragma unroll
    for (int off = 16; off > 0; off >>= 1)
        ss += __shfl_xor_sync(0xffffffffu, ss, off);
    float den = fmaxf(__fsqrt_rn(ss), 1e-12f);
    float2 o;
    o.x = __fdiv_rn(va, den);
    o.y = __fdiv_rn(vb, den);
    reinterpret_cast<float2*>(g_rest_tok)[t*32 + lane] = o;
    if (lane == 0) g_key[t] = 0ull;         // all valid keys are > 0
}

// ------- cosine argmax SMALL (ntok in {32,64,128,256}): subsplit layout ----
__global__ void __launch_bounds__(256) argmax_small_kernel(int ntok) {
    __shared__ __align__(16) float4 s_cb[TR*16];   // 32KB tile
    int tid = threadIdx.x;
    int tg  = tid & (ntok - 1);
    int sub = tid / ntok;
    int subs = 256 / ntok;
    int rps = TR / subs;

    unsigned long long tok[32];
    {
        const ulonglong2* p =
            reinterpret_cast<const ulonglong2*>(g_rest_tok + tg*CC);
        #pragma unroll
        for (int j = 0; j < 16; ++j) {
            ulonglong2 u = p[j];
            tok[2*j]   = u.x;
            tok[2*j+1] = u.y;
        }
    }

    int vstart = blockIdx.y * TR;
    {
        const float4* src = reinterpret_cast<const float4*>(g_cbn)
                          + (size_t)vstart * 16;
        #pragma unroll
        for (int k = 0; k < (TR*16)/256; ++k)
            s_cb[tid + k*256] = src[tid + k*256];
    }
    __syncthreads();

    const ulonglong2* cb = reinterpret_cast<const ulonglong2*>(s_cb);
    int r0 = sub * rps;

    float best = -1e30f; int bidx = 0;
    ulonglong2 bufA[8], bufB[8];
    #pragma unroll
    for (int j = 0; j < 8; ++j) bufA[j] = cb[r0*16 + j];

    #pragma unroll 1
    for (int row = r0; row < r0 + rps; ++row) {
        unsigned long long a01 = 0ull, a23 = 0ull;
        #pragma unroll
        for (int j = 0; j < 8; ++j) bufB[j] = cb[row*16 + 8 + j];
        #pragma unroll
        for (int j = 0; j < 8; ++j) {
            FMA_F32X2(a01, bufA[j].x, tok[2*j],   a01);
            FMA_F32X2(a23, bufA[j].y, tok[2*j+1], a23);
        }
        if (row + 1 < r0 + rps) {
            #pragma unroll
            for (int j = 0; j < 8; ++j) bufA[j] = cb[(row+1)*16 + j];
        }
        #pragma unroll
        for (int j = 8; j < 16; ++j) {
            FMA_F32X2(a01, bufB[j-8].x, tok[2*j],   a01);
            FMA_F32X2(a23, bufB[j-8].y, tok[2*j+1], a23);
        }
        unsigned x0, x1, x2, x3;
        UNPACK_F32X2(x0, x1, a01);
        UNPACK_F32X2(x2, x3, a23);
        float d = (__uint_as_float(x0) + __uint_as_float(x1))
                + (__uint_as_float(x2) + __uint_as_float(x3));
        if (d > best) { best = d; bidx = vstart + row; }
    }

    atomicMax(&g_key[tg], pack_key(best, bidx));
}

// ------------- cosine argmax TPT2 (ntok>=512): 2 tok/thread, FULL-ROW ------
// double buffering: prefetch row k+1 (16 LDS) spread across the 32 FMA2 of
// row k -> prefetch distance ~64 issue-cyc >> 29-cyc LDS latency. Per-dot
// chains bit-identical (j=0..15 sequential a01/a23, (ax+ay)+(az+aw)).
__global__ void __launch_bounds__(256) argmax2_kernel(int ntok, int chunk) {
    __shared__ __align__(16) float4 s_cb[TR*16];   // 32KB tile

    int tid = threadIdx.x;
    int tgA = blockIdx.x * 512 + tid;
    int tgB = tgA + 256;
    int cA = (tgA < ntok) ? tgA : (ntok - 1);
    int cB = (tgB < ntok) ? tgB : (ntok - 1);

    unsigned long long ta[32], tb[32];
    {
        const ulonglong2* p =
            reinterpret_cast<const ulonglong2*>(g_rest_tok + cA*CC);
        const ulonglong2* q =
            reinterpret_cast<const ulonglong2*>(g_rest_tok + cB*CC);
        #pragma unroll
        for (int j = 0; j < 16; ++j) {
            ulonglong2 u = p[j]; ta[2*j] = u.x; ta[2*j+1] = u.y;
            ulonglong2 w = q[j]; tb[2*j] = w.x; tb[2*j+1] = w.y;
        }
    }

    float bestA = -1e30f, bestB = -1e30f; int idxA = 0, idxB = 0;
    int vstart = blockIdx.y * chunk;
    int ntiles = chunk / TR;

    for (int tile = 0; tile < ntiles; ++tile) {
        __syncthreads();
        const float4* src = reinterpret_cast<const float4*>(g_cbn)
                          + (size_t)(vstart + tile*TR) * 16;
        #pragma unroll
        for (int k = 0; k < (TR*16)/256; ++k)
            s_cb[tid + k*256] = src[tid + k*256];
        __syncthreads();

        const ulonglong2* cb = reinterpret_cast<const ulonglong2*>(s_cb);
        int vbase = vstart + tile*TR;

        ulonglong2 cur[16], nxt[16];
        #pragma unroll
        for (int j = 0; j < 16; ++j) cur[j] = cb[j];            // row 0

        #pragma unroll 1
        for (int row = 0; row < TR; row += 2) {
            // prefetch row+1 while computing row (cur)
            #pragma unroll
            for (int j = 0; j < 16; ++j) nxt[j] = cb[(row+1)*16 + j];
            {
                unsigned long long a01A = 0ull, a23A = 0ull;
                unsigned long long a01B = 0ull, a23B = 0ull;
                #pragma unroll
                for (int j = 0; j < 16; ++j) {
                    FMA_F32X2(a01A, cur[j].x, ta[2*j],   a01A);
                    FMA_F32X2(a23A, cur[j].y, ta[2*j+1], a23A);
                    FMA_F32X2(a01B, cur[j].x, tb[2*j],   a01B);
                    FMA_F32X2(a23B, cur[j].y, tb[2*j+1], a23B);
                }
                unsigned x0, x1, x2, x3;
                UNPACK_F32X2(x0, x1, a01A);
                UNPACK_F32X2(x2, x3, a23A);
                float dA = (__uint_as_float(x0) + __uint_as_float(x1))
                         + (__uint_as_float(x2) + __uint_as_float(x3));
                if (dA > bestA) { bestA = dA; idxA = vbase + row; }
                UNPACK_F32X2(x0, x1, a01B);
                UNPACK_F32X2(x2, x3, a23B);
                float dB = (__uint_as_float(x0) + __uint_as_float(x1))
                         + (__uint_as_float(x2) + __uint_as_float(x3));
                if (dB > bestB) { bestB = dB; idxB = vbase + row; }
            }
            // prefetch row+2 while computing row+1 (nxt)
            if (row + 2 < TR) {
                #pragma unroll
                for (int j = 0; j < 16; ++j) cur[j] = cb[(row+2)*16 + j];
            }
            {
                unsigned long long a01A = 0ull, a23A = 0ull;
                unsigned long long a01B = 0ull, a23B = 0ull;
                #pragma unroll
                for (int j = 0; j < 16; ++j) {
                    FMA_F32X2(a01A, nxt[j].x, ta[2*j],   a01A);
                    FMA_F32X2(a23A, nxt[j].y, ta[2*j+1], a23A);
                    FMA_F32X2(a01B, nxt[j].x, tb[2*j],   a01B);
                    FMA_F32X2(a23B, nxt[j].y, tb[2*j+1], a23B);
                }
                unsigned x0, x1, x2, x3;
                UNPACK_F32X2(x0, x1, a01A);
                UNPACK_F32X2(x2, x3, a23A);
                float dA = (__uint_as_float(x0) + __uint_as_float(x1))
                         + (__uint_as_float(x2) + __uint_as_float(x3));
                if (dA > bestA) { bestA = dA; idxA = vbase + row + 1; }
                UNPACK_F32X2(x0, x1, a01B);
                UNPACK_F32X2(x2, x3, a23B);
                float dB = (__uint_as_float(x0) + __uint_as_float(x1))
                         + (__uint_as_float(x2) + __uint_as_float(x3));
                if (dB > bestB) { bestB = dB; idxB = vbase + row + 1; }
            }
        }
    }

    if (tgA < ntok) atomicMax(&g_key[tgA], pack_key(bestA, idxA));
    if (tgB < ntok) atomicMax(&g_key[tgB], pack_key(bestB, idxB));
}

// ---------------- fused gather + upsample + Phi conv + residual update + loss ----------------
#define TL 64
#define PHI_SMEM_FLOATS (CC*(TL+2) + CC*193 + CC)
__global__ void __launch_bounds__(256) phi_update_kernel(
    const float* __restrict__ f, const float* __restrict__ ew,
    const float* __restrict__ phiw, const float* __restrict__ phib,
    int s, int pidx, int first, float* __restrict__ outp)
{
    extern __shared__ float sm[];
    float* tile = sm;                 // [64][66]
    float* ws   = sm + CC*(TL+2);     // [64][193]
    float* bs   = ws + CC*193;        // [64]

    int b  = blockIdx.x >> 3;
    int l0 = (blockIdx.x & 7) * TL;
    int tid = threadIdx.x;

    const float* wsrc = phiw + pidx*CC*CC*3;
    for (int i = tid; i < CC*192; i += 256) {
        int co = i / 192, rem = i - co*192;
        ws[co*193 + rem] = wsrc[i];
    }
    if (tid < CC) bs[tid] = phib[pidx*CC + tid];

    for (int i = tid; i < CC*(TL+2); i += 256) {
        int ci = i / (TL+2), j = i - ci*(TL+2);
        int l = l0 + j - 1;
        float v = 0.f;
        if (l >= 0 && l < LL) {
            int tokp = (l * s) >> 9;
            int code = VV - (int)(unsigned)(g_key[b*s + tokp] & 0xffffffffu);
            v = ew[code*CC + ci];
        }
        tile[ci*(TL+2) + j] = v;
    }
    __syncthreads();

    int co = tid & 63;
    int pbase = (tid >> 6) * 16;
    float acc[16];
    #pragma unroll
    for (int p = 0; p < 16; ++p) acc[p] = 0.f;

    for (int ci = 0; ci < CC; ++ci) {
        const float* wr = ws + co*193 + ci*3;
        float w0 = wr[0], w1 = wr[1], w2 = wr[2];
        const float* hr = tile + ci*(TL+2) + pbase;
        float h[18];
        #pragma unroll
        for (int j = 0; j < 18; ++j) h[j] = hr[j];
        #pragma unroll
        for (int p = 0; p < 16; ++p)
            acc[p] = fmaf(w0, h[p], fmaf(w1, h[p+1], fmaf(w2, h[p+2], acc[p])));
    }

    float ss = 0.f;
    float bb = bs[co];
    #pragma unroll
    for (int p = 0; p < 16; ++p) {
        int l = l0 + pbase + p;
        float hc = tile[co*(TL+2) + pbase + p + 1];
        float y = 0.5f*hc + 0.5f*(acc[p] + bb);
        int gi = (b*CC + co)*LL + l;
        float fh = first ? y : (g_fhat[gi] + y);
        if (outp) {
            outp[gi] = fh;                 // last scale: write output directly
        } else {
            g_fhat[gi] = fh;
            g_frest[gi] = (first ? f[gi] : g_frest[gi]) - y;
        }
        float d = fh - f[gi];
        ss = fmaf(d, d, ss);
    }

    #pragma unroll
    for (int off = 16; off > 0; off >>= 1)
        ss += __shfl_xor_sync(0xffffffffu, ss, off);
    __shared__ float red[8];
    int lane = tid & 31, warp = tid >> 5;
    if (lane == 0) red[warp] = ss;
    __syncthreads();
    if (tid == 0) {
        float tot = 0.f;
        #pragma unroll
        for (int w = 0; w < 8; ++w) tot += red[w];
        atomicAdd(&g_loss, tot);
    }
}

// ---------------- tail: loss scalar (+ zero any padding) ----------------
__global__ void loss_kernel(float* __restrict__ out, int out_size) {
    int i = NELEM + blockIdx.x*256 + threadIdx.x;
    if (i >= out_size) return;
    out[i] = (i == NELEM) ? g_loss * (1.25f / (10.0f * (float)NELEM)) : 0.f;
}

// ---------------- launch ----------------
extern "C" void kernel_launch(void* const* d_in, const int* in_sizes, int n_in,
                              void* d_out, int out_size) {
    // Bind inputs BY ELEMENT COUNT (pairwise distinct -> ordering-immune)
    const float* f    = nullptr;
    const float* ew   = nullptr;
    const float* phiw = nullptr;
    const float* phib = nullptr;
    for (int i = 0; i < n_in; ++i) {
        switch (in_sizes[i]) {
            case 1048576: f    = (const float*)d_in[i]; break;
            case 524288:  ew   = (const float*)d_in[i]; break;
            case 49152:   phiw = (const float*)d_in[i]; break;
            case 256:     phib = (const float*)d_in[i]; break;
            default: break;
        }
    }
    float* out = (float*)d_out;

    const int seg[10] = {1,2,4,8,16,32,64,128,256,512};

    // pmap: bit-exact float64 replication of np.linspace + np.argmin(first-wins)
    int pmap[10];
    {
        double start = 1.0 / 12.0;
        double stop  = 1.0 - 1.0 / 12.0;
        double delta = stop - start;
        double step  = delta / 3.0;
        double ticks[4];
        for (int i = 0; i < 4; ++i) ticks[i] = (double)i * step + start;
        ticks[3] = stop;
        for (int si = 0; si < 10; ++si) {
            double x = (double)si / 9.0;
            int best = 0;
            double bd = fabs(ticks[0] - x);
            for (int i = 1; i < 4; ++i) {
                double d = fabs(ticks[i] - x);
                if (d < bd) { bd = d; best = i; }
            }
            pmap[si] = best;
        }
    }

    cudaFuncSetAttribute(phi_update_kernel,
                         cudaFuncAttributeMaxDynamicSharedMemorySize,
                         PHI_SMEM_FLOATS * (int)sizeof(float));

    normalize_cb_kernel<<<VV, 32>>>(ew);

    // resolve g_frest device address once (host-side; not a stream op)
    float* frest_ptr = nullptr;
    cudaGetSymbolAddress((void**)&frest_ptr, g_frest);

    for (int si = 0; si < 10; ++si) {
        int s = seg[si];
        int ntok = BB * s;
        int r = LL / s;

        ds_norm_kernel<<<(ntok + 7)/8, 256>>>(si == 0 ? f : frest_ptr, s, r, ntok);

        if (ntok >= 512) {
            int xblocks = ntok / 512;              // exact (ntok multiple of 512)
            int vs = 1;
            while (xblocks * vs < 296 && vs < 64) vs <<= 1;
            int chunk = VV / vs;                   // multiple of TR=128
            dim3 agrid(xblocks, vs);
            argmax2_kernel<<<agrid, 256>>>(ntok, chunk);
        } else {
            dim3 agrid(1, VV / TR);                // 64 tile-blocks
            argmax_small_kernel<<<agrid, 256>>>(ntok);
        }

        phi_update_kernel<<<BB*8, 256, PHI_SMEM_FLOATS*(int)sizeof(float)>>>(
            f, ew, phiw, phib, s, pmap[si], si == 0 ? 1 : 0,
            (si == 9) ? out : nullptr);
    }

    loss_kernel<<<(out_size - NELEM + 255)/256, 256>>>(out, out_size);
}